// round 9
// baseline (speedup 1.0000x reference)
#include <cuda_runtime.h>
#include <cstdint>
#include <math.h>

#define Bn 8
#define Tn 2048
#define Cn 1024
#define Hn 64

// ---------------- device scratch (sanctioned no-alloc path) ----------------
__device__ float g_q[Bn * Tn * Hn];
__device__ float g_k[Bn * Tn * Hn];
__device__ float g_v[Bn * Tn * Hn];                 // V fp32 [b][t][h]
__device__ unsigned short g_vht[Bn * Hn * Tn];      // V bf16 hi, transposed [b][h][t]
__device__ unsigned short g_vlt[Bn * Hn * Tn];      // V bf16 lo, transposed
__device__ unsigned short g_wt_hi[3 * Hn * Cn];     // W bf16 hi, [o*64+n][k]
__device__ unsigned short g_wt_lo[3 * Hn * Cn];     // W bf16 lo

__device__ __forceinline__ float tf32_round(float x) {
    uint32_t u;
    asm("cvt.rna.tf32.f32 %0, %1;" : "=r"(u) : "f"(x));
    return __uint_as_float(u);
}
__device__ __forceinline__ uint32_t bfpack(float hi, float lo) {
    uint32_t d;
    asm("cvt.rn.bf16x2.f32 %0, %1, %2;" : "=r"(d) : "f"(hi), "f"(lo));
    return d;
}
__device__ __forceinline__ uint32_t smem_u32(const void* p) {
    uint32_t a;
    asm("{ .reg .u64 t; cvta.to.shared.u64 t, %1; cvt.u32.u64 %0, t; }" : "=r"(a) : "l"(p));
    return a;
}
__device__ __forceinline__ void cp16(uint32_t s, const void* g) {
    asm volatile("cp.async.cg.shared.global [%0], [%1], 16;" :: "r"(s), "l"(g));
}
#define CP_COMMIT() asm volatile("cp.async.commit_group;" ::: "memory")
#define CP_WAIT1()  asm volatile("cp.async.wait_group 1;" ::: "memory")
#define CP_WAIT0()  asm volatile("cp.async.wait_group 0;" ::: "memory")

__device__ __forceinline__ void mma_tf32(float* c, const uint32_t* a, const uint32_t* b) {
    asm volatile(
        "mma.sync.aligned.m16n8k8.row.col.f32.tf32.tf32.f32 "
        "{%0,%1,%2,%3}, {%4,%5,%6,%7}, {%8,%9}, {%0,%1,%2,%3};"
        : "+f"(c[0]), "+f"(c[1]), "+f"(c[2]), "+f"(c[3])
        : "r"(a[0]), "r"(a[1]), "r"(a[2]), "r"(a[3]), "r"(b[0]), "r"(b[1]));
}
__device__ __forceinline__ void mma_bf16(float* c, const uint32_t* a, const uint32_t* b) {
    asm volatile(
        "mma.sync.aligned.m16n8k16.row.col.f32.bf16.bf16.f32 "
        "{%0,%1,%2,%3}, {%4,%5,%6,%7}, {%8,%9}, {%0,%1,%2,%3};"
        : "+f"(c[0]), "+f"(c[1]), "+f"(c[2]), "+f"(c[3])
        : "r"(a[0]), "r"(a[1]), "r"(a[2]), "r"(a[3]), "r"(b[0]), "r"(b[1]));
}

// ---------------------------------------------------------------------------
// prep: transpose weights to [o][n][k], bf16 Dekker split.
// ---------------------------------------------------------------------------
__global__ void prep_w(const float* __restrict__ Wk, const float* __restrict__ Wq,
                       const float* __restrict__ Wv) {
    int idx = blockIdx.x * 256 + threadIdx.x;
    int o = idx / (Hn * Cn);
    int rem = idx - o * (Hn * Cn);
    int n = rem / Cn;
    int k = rem - n * Cn;
    const float* W = (o == 0) ? Wq : (o == 1) ? Wk : Wv;
    float v = W[k * Hn + n];
    uint32_t p = bfpack(v, v);
    float fb = __uint_as_float(p & 0xFFFF0000u);
    uint32_t pl = bfpack(v - fb, v - fb);
    g_wt_hi[idx] = (unsigned short)(p >> 16);
    g_wt_lo[idx] = (unsigned short)(pl >> 16);
}

// ---------------------------------------------------------------------------
// V transpose + bf16 split: g_v [t][h] f32 -> g_vht/g_vlt [h][t] bf16.
// ---------------------------------------------------------------------------
__global__ __launch_bounds__(128) void vt_split() {
    __shared__ float ts[64][65];
    const int b = blockIdx.y, t0 = blockIdx.x * 64;
    const int t = threadIdx.x;
    const float* vin = &g_v[((size_t)b * Tn + t0) * Hn];
    #pragma unroll
    for (int i = 0; i < 8; i++) {
        int c = t + i * 128;
        int r = c >> 4, c4 = (c & 15) * 4;
        float4 v = *(const float4*)&vin[r * Hn + c4];
        ts[r][c4] = v.x; ts[r][c4 + 1] = v.y; ts[r][c4 + 2] = v.z; ts[r][c4 + 3] = v.w;
    }
    __syncthreads();
    #pragma unroll
    for (int i = 0; i < 16; i++) {
        int c = t + i * 128;
        int h = c >> 5, c2 = (c & 31) * 2;
        float v0 = ts[c2][h], v1 = ts[c2 + 1][h];
        uint32_t ph = bfpack(v1, v0);
        float f0 = __uint_as_float(ph << 16);
        float f1 = __uint_as_float(ph & 0xFFFF0000u);
        uint32_t pl = bfpack(v1 - f1, v0 - f0);
        size_t o = (size_t)(b * Hn + h) * Tn + t0 + c2;
        *(uint32_t*)&g_vht[o] = ph;
        *(uint32_t*)&g_vlt[o] = pl;
    }
}

// ---------------------------------------------------------------------------
// QKV via mma.sync bf16 k16, 3-term split, cp.async double-buffered.
// CTA: 64 rows x 192 cols, 8 warps as 2(m) x 4(n), warp tile m32n48 (mf=2).
// Stage: A f32 64x40 (10240 B) + Bh/Bl bf16 192x40 (15360 B each) = 40960 B.
// Grid 256 -> 2 CTAs/SM, 4 warps/SMSP.
// ---------------------------------------------------------------------------
#define QAST 40
#define QKV_STAGE_B 40960
#define QKV_SMEM (2 * QKV_STAGE_B)

__global__ __launch_bounds__(256, 2) void qkv_mma(
    const float* __restrict__ x,
    const float* __restrict__ bk, const float* __restrict__ bq, const float* __restrict__ bv)
{
    extern __shared__ char smc[];
    const uint32_t sb = smem_u32(smc);
    const int t = threadIdx.x;
    const int wid = t >> 5, lane = t & 31;
    const int wm = wid >> 2, wn = wid & 3;
    const int g = lane >> 2, tg = lane & 3;
    const int m0 = blockIdx.x * 64;

    float c[2][6][4];
    #pragma unroll
    for (int mf = 0; mf < 2; mf++)
        #pragma unroll
        for (int nf = 0; nf < 6; nf++)
            #pragma unroll
            for (int r = 0; r < 4; r++) c[mf][nf][r] = 0.0f;

    auto issue = [&](int ch, int st) {
        const int k0 = ch * 32;
        uint32_t sA = sb + (uint32_t)st * QKV_STAGE_B;
        uint32_t sBh = sA + 10240;
        uint32_t sBl = sBh + 15360;
        #pragma unroll
        for (int i = 0; i < 2; i++) {
            int cc = t + i * 256;            // 512 chunks: 64 rows x 8
            int r = cc >> 3, o = cc & 7;
            cp16(sA + r * 160 + o * 16, &x[(size_t)(m0 + r) * Cn + k0 + o * 4]);
        }
        #pragma unroll
        for (int i = 0; i < 3; i++) {
            int cc = t + i * 256;            // 768 chunks: 192 rows x 4
            int r = cc >> 2, o = cc & 3;
            cp16(sBh + r * 80 + o * 16,
                 (const char*)g_wt_hi + ((size_t)r * Cn + k0 + o * 8) * 2);
            cp16(sBl + r * 80 + o * 16,
                 (const char*)g_wt_lo + ((size_t)r * Cn + k0 + o * 8) * 2);
        }
    };

    issue(0, 0);
    CP_COMMIT();

    for (int ch = 0; ch < 32; ch++) {
        if (ch < 31) { issue(ch + 1, (ch + 1) & 1); CP_COMMIT(); CP_WAIT1(); }
        else         { CP_WAIT0(); }
        __syncthreads();

        char* stg = smc + (ch & 1) * QKV_STAGE_B;
        const float* As = (const float*)stg;
        const uint32_t* Bhu = (const uint32_t*)(stg + 10240);
        const uint32_t* Blu = (const uint32_t*)(stg + 25600);

        #pragma unroll
        for (int ks = 0; ks < 2; ks++) {
            const int kk = ks * 16;
            uint32_t a_h[2][4], a_l[2][4], b_h[6][2], b_l[6][2];
            #pragma unroll
            for (int mf = 0; mf < 2; mf++) {
                int row = wm * 32 + mf * 16 + g;
                float2 p0 = *(const float2*)&As[row * QAST + kk + 2 * tg];
                float2 p1 = *(const float2*)&As[(row + 8) * QAST + kk + 2 * tg];
                float2 p2 = *(const float2*)&As[row * QAST + kk + 8 + 2 * tg];
                float2 p3 = *(const float2*)&As[(row + 8) * QAST + kk + 8 + 2 * tg];
                float2 ps[4] = {p0, p1, p2, p3};
                #pragma unroll
                for (int q = 0; q < 4; q++) {
                    uint32_t ph = bfpack(ps[q].y, ps[q].x);
                    a_h[mf][q] = ph;
                    float f0 = __uint_as_float(ph << 16);
                    float f1 = __uint_as_float(ph & 0xFFFF0000u);
                    a_l[mf][q] = bfpack(ps[q].y - f1, ps[q].x - f0);
                }
            }
            #pragma unroll
            for (int nf = 0; nf < 6; nf++) {
                int n = wn * 48 + nf * 8 + g;
                int ab = n * 20 + ks * 8 + tg;
                b_h[nf][0] = Bhu[ab];
                b_h[nf][1] = Bhu[ab + 4];
                b_l[nf][0] = Blu[ab];
                b_l[nf][1] = Blu[ab + 4];
            }
            #pragma unroll
            for (int nf = 0; nf < 6; nf++)
                #pragma unroll
                for (int mf = 0; mf < 2; mf++)
                    mma_bf16(c[mf][nf], a_h[mf], b_h[nf]);
            #pragma unroll
            for (int nf = 0; nf < 6; nf++)
                #pragma unroll
                for (int mf = 0; mf < 2; mf++)
                    mma_bf16(c[mf][nf], a_h[mf], b_l[nf]);
            #pragma unroll
            for (int nf = 0; nf < 6; nf++)
                #pragma unroll
                for (int mf = 0; mf < 2; mf++)
                    mma_bf16(c[mf][nf], a_l[mf], b_h[nf]);
        }
        __syncthreads();
    }

    // epilogue: bias
    #pragma unroll
    for (int nf = 0; nf < 6; nf++) {
        int col = wn * 48 + nf * 8 + tg * 2;
        int o = col >> 6;
        int h = col & 63;
        float* gout = (o == 0) ? g_q : (o == 1) ? g_k : g_v;
        const float* bias = (o == 0) ? bq : (o == 1) ? bk : bv;
        float2 bb = *(const float2*)&bias[h];
        #pragma unroll
        for (int mf = 0; mf < 2; mf++) {
            int r0 = m0 + wm * 32 + mf * 16 + g;
            *(float2*)&gout[(size_t)r0 * Hn + h] =
                make_float2(c[mf][nf][0] + bb.x, c[mf][nf][1] + bb.y);
            *(float2*)&gout[(size_t)(r0 + 8) * Hn + h] =
                make_float2(c[mf][nf][2] + bb.x, c[mf][nf][3] + bb.y);
        }
    }
}

// ---------------------------------------------------------------------------
// Flash attention: S = tf32 k8, PV = bf16 k16 3-term, thread-local P packing.
// Grid (32, 8) = 256 CTAs (one q-tile each) -> 2 CTAs/SM co-resident.
// Stage: K 64x68 f32 (17408) + VhT 64x36 u32 (9216) + VlT (9216) = 35840 B.
// ---------------------------------------------------------------------------
#define KST 68
#define ATT_STAGE_B 35840
#define ATTN_SMEM (2 * ATT_STAGE_B)

__global__ __launch_bounds__(128, 2) void attn_mma(float* __restrict__ out)
{
    extern __shared__ char smc[];
    const uint32_t sb = smem_u32(smc);

    const int t = threadIdx.x;
    const int w = t >> 5, lane = t & 31;
    const int g = lane >> 2, tg = lane & 3;
    const int b = blockIdx.y;
    const long base = (long)b * Tn * Hn;
    const float scale = 0.03125f;     // 1024^-0.5

    auto issue = [&](int k0, int st) {
        uint32_t sK = sb + (uint32_t)st * ATT_STAGE_B;
        uint32_t sVh = sK + 17408;
        uint32_t sVl = sVh + 9216;
        #pragma unroll
        for (int i = 0; i < 8; i++) {
            int r = (t >> 4) + i * 8;
            int c4 = (t & 15) * 4;
            cp16(sK + (r * KST + c4) * 4, &g_k[base + (long)(k0 + r) * Hn + c4]);
        }
        #pragma unroll
        for (int i = 0; i < 4; i++) {
            int cc = t + i * 128;
            int h = cc >> 3, o = cc & 7;
            size_t go = ((size_t)(b * Hn + h) * Tn + k0 + o * 8) * 2;
            cp16(sVh + h * 144 + o * 16, (const char*)g_vht + go);
            cp16(sVl + h * 144 + o * 16, (const char*)g_vlt + go);
        }
    };

    const int qi = blockIdx.x;
    const int q0 = qi * 64;
    const int rw = w * 16 + g;

    issue(0, 0);
    CP_COMMIT();

    uint32_t qa[8][4];
    {
        const float* qp = &g_q[base + (long)(q0 + rw) * Hn];
        #pragma unroll
        for (int ksi = 0; ksi < 8; ksi++) {
            qa[ksi][0] = __float_as_uint(tf32_round(qp[ksi * 8 + tg] * scale));
            qa[ksi][1] = __float_as_uint(tf32_round(qp[8 * Hn + ksi * 8 + tg] * scale));
            qa[ksi][2] = __float_as_uint(tf32_round(qp[ksi * 8 + tg + 4] * scale));
            qa[ksi][3] = __float_as_uint(tf32_round(qp[8 * Hn + ksi * 8 + tg + 4] * scale));
        }
    }

    float m0 = -1e30f, m1 = -1e30f, l0 = 0.0f, l1 = 0.0f;
    float o[8][4];
    #pragma unroll
    for (int nf = 0; nf < 8; nf++)
        #pragma unroll
        for (int r = 0; r < 4; r++) o[nf][r] = 0.0f;

    for (int j = 0; j <= qi; j++) {
        if (j < qi) { issue((j + 1) * 64, (j + 1) & 1); CP_COMMIT(); CP_WAIT1(); }
        else        { CP_WAIT0(); }
        __syncthreads();

        char* stg = smc + (j & 1) * ATT_STAGE_B;
        const float* ksm = (const float*)stg;
        const uint32_t* vhu = (const uint32_t*)(stg + 17408);
        const uint32_t* vlu = (const uint32_t*)(stg + 26624);

        // ---- S = Qs . K^T ----
        float s[8][4];
        #pragma unroll
        for (int nf = 0; nf < 8; nf++)
            #pragma unroll
            for (int r = 0; r < 4; r++) s[nf][r] = 0.0f;

        #pragma unroll
        for (int ksi = 0; ksi < 8; ksi++) {
            uint32_t bf[8][2];
            #pragma unroll
            for (int nf = 0; nf < 8; nf++) {
                int a = (nf * 8 + g) * KST + ksi * 8 + tg;
                bf[nf][0] = __float_as_uint(ksm[a]);
                bf[nf][1] = __float_as_uint(ksm[a + 4]);
            }
            #pragma unroll
            for (int nf = 0; nf < 8; nf++)
                mma_tf32(s[nf], qa[ksi], bf[nf]);
        }

        if (j == qi) {
            #pragma unroll
            for (int nf = 0; nf < 8; nf++) {
                int col = nf * 8 + 2 * tg;
                if (col     > rw)     s[nf][0] = -1e30f;
                if (col + 1 > rw)     s[nf][1] = -1e30f;
                if (col     > rw + 8) s[nf][2] = -1e30f;
                if (col + 1 > rw + 8) s[nf][3] = -1e30f;
            }
        }

        // ---- online softmax ----
        float mx0 = -1e30f, mx1 = -1e30f;
        #pragma unroll
        for (int nf = 0; nf < 8; nf++) {
            mx0 = fmaxf(mx0, fmaxf(s[nf][0], s[nf][1]));
            mx1 = fmaxf(mx1, fmaxf(s[nf][2], s[nf][3]));
        }
        #pragma unroll
        for (int off = 1; off <= 2; off <<= 1) {
            mx0 = fmaxf(mx0, __shfl_xor_sync(0xffffffffu, mx0, off));
            mx1 = fmaxf(mx1, __shfl_xor_sync(0xffffffffu, mx1, off));
        }
        float mn0 = fmaxf(m0, mx0), mn1 = fmaxf(m1, mx1);
        float rs0 = 0.0f, rs1 = 0.0f;
        #pragma unroll
        for (int nf = 0; nf < 8; nf++) {
            s[nf][0] = __expf(s[nf][0] - mn0);
            s[nf][1] = __expf(s[nf][1] - mn0);
            s[nf][2] = __expf(s[nf][2] - mn1);
            s[nf][3] = __expf(s[nf][3] - mn1);
            rs0 += s[nf][0] + s[nf][1];
            rs1 += s[nf][2] + s[nf][3];
        }
        #pragma unroll
        for (int off = 1; off <= 2; off <<= 1) {
            rs0 += __shfl_xor_sync(0xffffffffu, rs0, off);
            rs1 += __shfl_xor_sync(0xffffffffu, rs1, off);
        }
        float a0 = __expf(m0 - mn0), a1 = __expf(m1 - mn1);
        l0 = l0 * a0 + rs0; m0 = mn0;
        l1 = l1 * a1 + rs1; m1 = mn1;
        #pragma unroll
        for (int nf = 0; nf < 8; nf++) {
            o[nf][0] *= a0; o[nf][1] *= a0;
            o[nf][2] *= a1; o[nf][3] *= a1;
        }

        // ---- O += P . V  (bf16 k16, 3 terms; thread-local A-frag packing) ----
        #pragma unroll
        for (int ksi = 0; ksi < 4; ksi++) {
            uint32_t ah[4], al[4];
            #pragma unroll
            for (int q = 0; q < 4; q++) {
                int sn = 2 * ksi + (q >> 1);
                int e = (q & 1) * 2;
                float s0 = s[sn][e], s1 = s[sn][e + 1];
                uint32_t ph = bfpack(s1, s0);
                ah[q] = ph;
                float f0 = __uint_as_float(ph << 16);
                float f1 = __uint_as_float(ph & 0xFFFF0000u);
                al[q] = bfpack(s1 - f1, s0 - f0);
            }
            uint32_t bh[8][2], bl[8][2];
            #pragma unroll
            for (int nf = 0; nf < 8; nf++) {
                int ab = (nf * 8 + g) * 36 + 8 * ksi + tg;
                bh[nf][0] = vhu[ab];
                bh[nf][1] = vhu[ab + 4];
                bl[nf][0] = vlu[ab];
                bl[nf][1] = vlu[ab + 4];
            }
            #pragma unroll
            for (int nf = 0; nf < 8; nf++)
                mma_bf16(o[nf], ah, bh[nf]);
            #pragma unroll
            for (int nf = 0; nf < 8; nf++)
                mma_bf16(o[nf], ah, bl[nf]);
            #pragma unroll
            for (int nf = 0; nf < 8; nf++)
                mma_bf16(o[nf], al, bh[nf]);
        }
        __syncthreads();
    }

    float inv0 = 1.0f / l0, inv1 = 1.0f / l1;
    #pragma unroll
    for (int nf = 0; nf < 8; nf++) {
        int col = nf * 8 + 2 * tg;
        long r0 = base + (long)(q0 + rw) * Hn + col;
        *(float2*)&out[r0]          = make_float2(o[nf][0] * inv0, o[nf][1] * inv0);
        *(float2*)&out[r0 + 8 * Hn] = make_float2(o[nf][2] * inv1, o[nf][3] * inv1);
    }
}

// ---------------------------------------------------------------------------
extern "C" void kernel_launch(void* const* d_in, const int* in_sizes, int n_in,
                              void* d_out, int out_size)
{
    const float* x  = (const float*)d_in[0];
    const float* Wk = (const float*)d_in[1];
    const float* bk = (const float*)d_in[2];
    const float* Wq = (const float*)d_in[3];
    const float* bq = (const float*)d_in[4];
    const float* Wv = (const float*)d_in[5];
    const float* bv = (const float*)d_in[6];
    float* out = (float*)d_out;

    prep_w<<<(3 * Hn * Cn) / 256, 256>>>(Wk, Wq, Wv);

    cudaFuncSetAttribute(qkv_mma, cudaFuncAttributeMaxDynamicSharedMemorySize, QKV_SMEM);
    qkv_mma<<<(Bn * Tn) / 64, 256, QKV_SMEM>>>(x, bk, bq, bv);

    vt_split<<<dim3(Tn / 64, Bn), 128>>>();

    cudaFuncSetAttribute(attn_mma, cudaFuncAttributeMaxDynamicSharedMemorySize, ATTN_SMEM);
    attn_mma<<<dim3(Tn / 64, Bn), 128, ATTN_SMEM>>>(out);
}

// round 10
// speedup vs baseline: 1.1194x; 1.1194x over previous
#include <cuda_runtime.h>
#include <cstdint>
#include <math.h>

#define Bn 8
#define Tn 2048
#define Cn 1024
#define Hn 64

// ---------------- device scratch (sanctioned no-alloc path) ----------------
__device__ float g_q[Bn * Tn * Hn];
__device__ float g_k[Bn * Tn * Hn];
__device__ float g_v[Bn * Tn * Hn];                 // V fp32 [b][t][h]
__device__ unsigned short g_vht[Bn * Hn * Tn];      // V bf16 hi, transposed [b][h][t]
__device__ unsigned short g_vlt[Bn * Hn * Tn];      // V bf16 lo, transposed
__device__ unsigned short g_wt_hi[3 * Hn * Cn];     // W bf16 hi, [o*64+n][k]
__device__ unsigned short g_wt_lo[3 * Hn * Cn];     // W bf16 lo

__device__ __forceinline__ float tf32_round(float x) {
    uint32_t u;
    asm("cvt.rna.tf32.f32 %0, %1;" : "=r"(u) : "f"(x));
    return __uint_as_float(u);
}
__device__ __forceinline__ uint32_t bfpack(float hi, float lo) {
    uint32_t d;
    asm("cvt.rn.bf16x2.f32 %0, %1, %2;" : "=r"(d) : "f"(hi), "f"(lo));
    return d;
}
__device__ __forceinline__ uint32_t smem_u32(const void* p) {
    uint32_t a;
    asm("{ .reg .u64 t; cvta.to.shared.u64 t, %1; cvt.u32.u64 %0, t; }" : "=r"(a) : "l"(p));
    return a;
}
__device__ __forceinline__ void cp16(uint32_t s, const void* g) {
    asm volatile("cp.async.cg.shared.global [%0], [%1], 16;" :: "r"(s), "l"(g));
}
#define CP_COMMIT() asm volatile("cp.async.commit_group;" ::: "memory")
#define CP_WAIT1()  asm volatile("cp.async.wait_group 1;" ::: "memory")
#define CP_WAIT0()  asm volatile("cp.async.wait_group 0;" ::: "memory")

__device__ __forceinline__ void mma_tf32(float* c, const uint32_t* a, const uint32_t* b) {
    asm volatile(
        "mma.sync.aligned.m16n8k8.row.col.f32.tf32.tf32.f32 "
        "{%0,%1,%2,%3}, {%4,%5,%6,%7}, {%8,%9}, {%0,%1,%2,%3};"
        : "+f"(c[0]), "+f"(c[1]), "+f"(c[2]), "+f"(c[3])
        : "r"(a[0]), "r"(a[1]), "r"(a[2]), "r"(a[3]), "r"(b[0]), "r"(b[1]));
}
__device__ __forceinline__ void mma_bf16(float* c, const uint32_t* a, const uint32_t* b) {
    asm volatile(
        "mma.sync.aligned.m16n8k16.row.col.f32.bf16.bf16.f32 "
        "{%0,%1,%2,%3}, {%4,%5,%6,%7}, {%8,%9}, {%0,%1,%2,%3};"
        : "+f"(c[0]), "+f"(c[1]), "+f"(c[2]), "+f"(c[3])
        : "r"(a[0]), "r"(a[1]), "r"(a[2]), "r"(a[3]), "r"(b[0]), "r"(b[1]));
}

// ---------------------------------------------------------------------------
// prep: transpose weights to [o][n][k], bf16 Dekker split.  (unchanged R8)
// ---------------------------------------------------------------------------
__global__ void prep_w(const float* __restrict__ Wk, const float* __restrict__ Wq,
                       const float* __restrict__ Wv) {
    int idx = blockIdx.x * 256 + threadIdx.x;
    int o = idx / (Hn * Cn);
    int rem = idx - o * (Hn * Cn);
    int n = rem / Cn;
    int k = rem - n * Cn;
    const float* W = (o == 0) ? Wq : (o == 1) ? Wk : Wv;
    float v = W[k * Hn + n];
    uint32_t p = bfpack(v, v);
    float fb = __uint_as_float(p & 0xFFFF0000u);
    uint32_t pl = bfpack(v - fb, v - fb);
    g_wt_hi[idx] = (unsigned short)(p >> 16);
    g_wt_lo[idx] = (unsigned short)(pl >> 16);
}

// ---------------------------------------------------------------------------
// V transpose + bf16 split (unchanged R8)
// ---------------------------------------------------------------------------
__global__ __launch_bounds__(128) void vt_split() {
    __shared__ float ts[64][65];
    const int b = blockIdx.y, t0 = blockIdx.x * 64;
    const int t = threadIdx.x;
    const float* vin = &g_v[((size_t)b * Tn + t0) * Hn];
    #pragma unroll
    for (int i = 0; i < 8; i++) {
        int c = t + i * 128;
        int r = c >> 4, c4 = (c & 15) * 4;
        float4 v = *(const float4*)&vin[r * Hn + c4];
        ts[r][c4] = v.x; ts[r][c4 + 1] = v.y; ts[r][c4 + 2] = v.z; ts[r][c4 + 3] = v.w;
    }
    __syncthreads();
    #pragma unroll
    for (int i = 0; i < 16; i++) {
        int c = t + i * 128;
        int h = c >> 5, c2 = (c & 31) * 2;
        float v0 = ts[c2][h], v1 = ts[c2 + 1][h];
        uint32_t ph = bfpack(v1, v0);
        float f0 = __uint_as_float(ph << 16);
        float f1 = __uint_as_float(ph & 0xFFFF0000u);
        uint32_t pl = bfpack(v1 - f1, v0 - f0);
        size_t o = (size_t)(b * Hn + h) * Tn + t0 + c2;
        *(uint32_t*)&g_vht[o] = ph;
        *(uint32_t*)&g_vlt[o] = pl;
    }
}

// ---------------------------------------------------------------------------
// QKV (byte-identical to the 133us R8 kernel: 128-row CTA, 256 thr, 1 CTA/SM)
// ---------------------------------------------------------------------------
#define QAST 40
#define QKV_STAGE_B 51200
#define QKV_SMEM (2 * QKV_STAGE_B)

__global__ __launch_bounds__(256) void qkv_mma(
    const float* __restrict__ x,
    const float* __restrict__ bk, const float* __restrict__ bq, const float* __restrict__ bv)
{
    extern __shared__ char smc[];
    const uint32_t sb = smem_u32(smc);
    const int t = threadIdx.x;
    const int wid = t >> 5, lane = t & 31;
    const int wm = wid >> 2, wn = wid & 3;
    const int g = lane >> 2, tg = lane & 3;
    const int m0 = blockIdx.x * 128;

    float c[4][6][4];
    #pragma unroll
    for (int mf = 0; mf < 4; mf++)
        #pragma unroll
        for (int nf = 0; nf < 6; nf++)
            #pragma unroll
            for (int r = 0; r < 4; r++) c[mf][nf][r] = 0.0f;

    auto issue = [&](int ch, int st) {
        const int k0 = ch * 32;
        uint32_t sA = sb + (uint32_t)st * QKV_STAGE_B;
        uint32_t sBh = sA + 20480;
        uint32_t sBl = sBh + 15360;
        #pragma unroll
        for (int i = 0; i < 4; i++) {
            int cc = t + i * 256;
            int r = cc >> 3, o = cc & 7;
            cp16(sA + r * 160 + o * 16, &x[(size_t)(m0 + r) * Cn + k0 + o * 4]);
        }
        #pragma unroll
        for (int i = 0; i < 3; i++) {
            int cc = t + i * 256;
            int r = cc >> 2, o = cc & 3;
            cp16(sBh + r * 80 + o * 16,
                 (const char*)g_wt_hi + ((size_t)r * Cn + k0 + o * 8) * 2);
            cp16(sBl + r * 80 + o * 16,
                 (const char*)g_wt_lo + ((size_t)r * Cn + k0 + o * 8) * 2);
        }
    };

    issue(0, 0);
    CP_COMMIT();

    for (int ch = 0; ch < 32; ch++) {
        if (ch < 31) { issue(ch + 1, (ch + 1) & 1); CP_COMMIT(); CP_WAIT1(); }
        else         { CP_WAIT0(); }
        __syncthreads();

        char* stg = smc + (ch & 1) * QKV_STAGE_B;
        const float* As = (const float*)stg;
        const uint32_t* Bhu = (const uint32_t*)(stg + 20480);
        const uint32_t* Blu = (const uint32_t*)(stg + 35840);

        #pragma unroll
        for (int ks = 0; ks < 2; ks++) {
            const int kk = ks * 16;
            uint32_t a_h[4][4], a_l[4][4], b_h[6][2], b_l[6][2];
            #pragma unroll
            for (int mf = 0; mf < 4; mf++) {
                int row = wm * 64 + mf * 16 + g;
                float2 p0 = *(const float2*)&As[row * QAST + kk + 2 * tg];
                float2 p1 = *(const float2*)&As[(row + 8) * QAST + kk + 2 * tg];
                float2 p2 = *(const float2*)&As[row * QAST + kk + 8 + 2 * tg];
                float2 p3 = *(const float2*)&As[(row + 8) * QAST + kk + 8 + 2 * tg];
                float2 ps[4] = {p0, p1, p2, p3};
                #pragma unroll
                for (int q = 0; q < 4; q++) {
                    uint32_t ph = bfpack(ps[q].y, ps[q].x);
                    a_h[mf][q] = ph;
                    float f0 = __uint_as_float(ph << 16);
                    float f1 = __uint_as_float(ph & 0xFFFF0000u);
                    a_l[mf][q] = bfpack(ps[q].y - f1, ps[q].x - f0);
                }
            }
            #pragma unroll
            for (int nf = 0; nf < 6; nf++) {
                int n = wn * 48 + nf * 8 + g;
                int ab = n * 20 + ks * 8 + tg;
                b_h[nf][0] = Bhu[ab];
                b_h[nf][1] = Bhu[ab + 4];
                b_l[nf][0] = Blu[ab];
                b_l[nf][1] = Blu[ab + 4];
            }
            #pragma unroll
            for (int nf = 0; nf < 6; nf++)
                #pragma unroll
                for (int mf = 0; mf < 4; mf++)
                    mma_bf16(c[mf][nf], a_h[mf], b_h[nf]);
            #pragma unroll
            for (int nf = 0; nf < 6; nf++)
                #pragma unroll
                for (int mf = 0; mf < 4; mf++)
                    mma_bf16(c[mf][nf], a_h[mf], b_l[nf]);
            #pragma unroll
            for (int nf = 0; nf < 6; nf++)
                #pragma unroll
                for (int mf = 0; mf < 4; mf++)
                    mma_bf16(c[mf][nf], a_l[mf], b_h[nf]);
        }
        __syncthreads();
    }

    #pragma unroll
    for (int nf = 0; nf < 6; nf++) {
        int col = wn * 48 + nf * 8 + tg * 2;
        int o = col >> 6;
        int h = col & 63;
        float* gout = (o == 0) ? g_q : (o == 1) ? g_k : g_v;
        const float* bias = (o == 0) ? bq : (o == 1) ? bk : bv;
        float2 bb = *(const float2*)&bias[h];
        #pragma unroll
        for (int mf = 0; mf < 4; mf++) {
            int r0 = m0 + wm * 64 + mf * 16 + g;
            *(float2*)&gout[(size_t)r0 * Hn + h] =
                make_float2(c[mf][nf][0] + bb.x, c[mf][nf][1] + bb.y);
            *(float2*)&gout[(size_t)(r0 + 8) * Hn + h] =
                make_float2(c[mf][nf][2] + bb.x, c[mf][nf][3] + bb.y);
        }
    }
}

// ---------------------------------------------------------------------------
// Flash attention, 256 threads: warp pair (p, p+4) shares 16 q-rows;
// half 0 = S cols 0-31 + PV k 0-31, half 1 = cols 32-63 + k 32-63.
// One smem LSE exchange per iter; O merged per q-tile. Balanced grid (16,8).
// Stage 35840 B x2 + 1KB exchange = 72704 B.
// ---------------------------------------------------------------------------
#define KST 68
#define ATT_STAGE_B 35840
#define ATTN_SMEM (2 * ATT_STAGE_B + 1024)

__global__ __launch_bounds__(256) void attn_mma(float* __restrict__ out)
{
    extern __shared__ char smc[];
    const uint32_t sb = smem_u32(smc);
    float* xch = (float*)(smc + 2 * ATT_STAGE_B);

    const int t = threadIdx.x;
    const int w = t >> 5, lane = t & 31;
    const int g = lane >> 2, tg = lane & 3;
    const int pairid = w & 3, half = w >> 2;
    const int b = blockIdx.y;
    const long base = (long)b * Tn * Hn;
    const float scale = 0.03125f;     // 1024^-0.5

    auto issue = [&](int k0, int st) {
        uint32_t sK = sb + (uint32_t)st * ATT_STAGE_B;
        uint32_t sVh = sK + 17408;
        uint32_t sVl = sVh + 9216;
        #pragma unroll
        for (int i = 0; i < 4; i++) {
            int cc = t + i * 256;            // 1024 chunks: 64 rows x 16
            int r = cc >> 4, c4 = (cc & 15) * 4;
            cp16(sK + (r * KST + c4) * 4, &g_k[base + (long)(k0 + r) * Hn + c4]);
        }
        #pragma unroll
        for (int i = 0; i < 2; i++) {
            int cc = t + i * 256;            // 512 chunks: 64 h-rows x 8
            int h = cc >> 3, o = cc & 7;
            size_t go = ((size_t)(b * Hn + h) * Tn + k0 + o * 8) * 2;
            cp16(sVh + h * 144 + o * 16, (const char*)g_vht + go);
            cp16(sVl + h * 144 + o * 16, (const char*)g_vlt + go);
        }
    };

    for (int tloop = 0; tloop < 2; tloop++) {
        const int qi = (tloop == 0) ? blockIdx.x : (31 - blockIdx.x);
        const int q0 = qi * 64;
        const int rw = pairid * 16 + g;

        issue(0, 0);
        CP_COMMIT();

        uint32_t qa[8][4];
        {
            const float* qp = &g_q[base + (long)(q0 + rw) * Hn];
            #pragma unroll
            for (int ksi = 0; ksi < 8; ksi++) {
                qa[ksi][0] = __float_as_uint(tf32_round(qp[ksi * 8 + tg] * scale));
                qa[ksi][1] = __float_as_uint(tf32_round(qp[8 * Hn + ksi * 8 + tg] * scale));
                qa[ksi][2] = __float_as_uint(tf32_round(qp[ksi * 8 + tg + 4] * scale));
                qa[ksi][3] = __float_as_uint(tf32_round(qp[8 * Hn + ksi * 8 + tg + 4] * scale));
            }
        }

        float m0 = -1e30f, m1 = -1e30f, l0 = 0.0f, l1 = 0.0f;
        float o[8][4];
        #pragma unroll
        for (int nf = 0; nf < 8; nf++)
            #pragma unroll
            for (int r = 0; r < 4; r++) o[nf][r] = 0.0f;

        for (int j = 0; j <= qi; j++) {
            if (j < qi) { issue((j + 1) * 64, (j + 1) & 1); CP_COMMIT(); CP_WAIT1(); }
            else        { CP_WAIT0(); }
            __syncthreads();

            char* stg = smc + (j & 1) * ATT_STAGE_B;
            const float* ksm = (const float*)stg;
            const uint32_t* vhu = (const uint32_t*)(stg + 17408);
            const uint32_t* vlu = (const uint32_t*)(stg + 26624);

            // ---- S = Qs . K^T  (this warp's 32 columns) ----
            float s[4][4];
            #pragma unroll
            for (int nf = 0; nf < 4; nf++)
                #pragma unroll
                for (int r = 0; r < 4; r++) s[nf][r] = 0.0f;

            #pragma unroll
            for (int ksi = 0; ksi < 8; ksi++) {
                uint32_t bf[4][2];
                #pragma unroll
                for (int nf = 0; nf < 4; nf++) {
                    int a = (half * 32 + nf * 8 + g) * KST + ksi * 8 + tg;
                    bf[nf][0] = __float_as_uint(ksm[a]);
                    bf[nf][1] = __float_as_uint(ksm[a + 4]);
                }
                #pragma unroll
                for (int nf = 0; nf < 4; nf++)
                    mma_tf32(s[nf], qa[ksi], bf[nf]);
            }

            if (j == qi) {
                #pragma unroll
                for (int nf = 0; nf < 4; nf++) {
                    int col = half * 32 + nf * 8 + 2 * tg;
                    if (col     > rw)     s[nf][0] = -1e30f;
                    if (col + 1 > rw)     s[nf][1] = -1e30f;
                    if (col     > rw + 8) s[nf][2] = -1e30f;
                    if (col + 1 > rw + 8) s[nf][3] = -1e30f;
                }
            }

            // ---- partial softmax over this warp's 32 columns ----
            float mx0 = -1e30f, mx1 = -1e30f;
            #pragma unroll
            for (int nf = 0; nf < 4; nf++) {
                mx0 = fmaxf(mx0, fmaxf(s[nf][0], s[nf][1]));
                mx1 = fmaxf(mx1, fmaxf(s[nf][2], s[nf][3]));
            }
            #pragma unroll
            for (int off = 1; off <= 2; off <<= 1) {
                mx0 = fmaxf(mx0, __shfl_xor_sync(0xffffffffu, mx0, off));
                mx1 = fmaxf(mx1, __shfl_xor_sync(0xffffffffu, mx1, off));
            }
            float rs0 = 0.0f, rs1 = 0.0f;
            #pragma unroll
            for (int nf = 0; nf < 4; nf++) {
                s[nf][0] = __expf(s[nf][0] - mx0);
                s[nf][1] = __expf(s[nf][1] - mx0);
                s[nf][2] = __expf(s[nf][2] - mx1);
                s[nf][3] = __expf(s[nf][3] - mx1);
                rs0 += s[nf][0] + s[nf][1];
                rs1 += s[nf][2] + s[nf][3];
            }
            #pragma unroll
            for (int off = 1; off <= 2; off <<= 1) {
                rs0 += __shfl_xor_sync(0xffffffffu, rs0, off);
                rs1 += __shfl_xor_sync(0xffffffffu, rs1, off);
            }

            // ---- LSE exchange with the peer warp ----
            if (tg == 0)
                *(float4*)&xch[((pairid * 8 + g) * 2 + half) * 4] =
                    make_float4(mx0, mx1, rs0, rs1);
            __syncthreads();
            float4 peer = *(const float4*)&xch[((pairid * 8 + g) * 2 + (half ^ 1)) * 4];

            float M0 = fmaxf(m0, fmaxf(mx0, peer.x));
            float M1 = fmaxf(m1, fmaxf(mx1, peer.y));
            float c0 = __expf(mx0 - M0), c1 = __expf(mx1 - M1);
            float a0 = __expf(m0 - M0), a1 = __expf(m1 - M1);
            l0 = l0 * a0 + rs0 * c0 + peer.z * __expf(peer.x - M0);
            l1 = l1 * a1 + rs1 * c1 + peer.w * __expf(peer.y - M1);
            m0 = M0; m1 = M1;
            #pragma unroll
            for (int nf = 0; nf < 8; nf++) {
                o[nf][0] *= a0; o[nf][1] *= a0;
                o[nf][2] *= a1; o[nf][3] *= a1;
            }
            #pragma unroll
            for (int nf = 0; nf < 4; nf++) {
                s[nf][0] *= c0; s[nf][1] *= c0;
                s[nf][2] *= c1; s[nf][3] *= c1;
            }

            // ---- O += P . V  (this warp's k-half; thread-local A packing) ----
            #pragma unroll
            for (int ksl = 0; ksl < 2; ksl++) {
                uint32_t ah[4], al[4];
                #pragma unroll
                for (int q = 0; q < 4; q++) {
                    int sn = 2 * ksl + (q >> 1);
                    int e = (q & 1) * 2;
                    float s0 = s[sn][e], s1 = s[sn][e + 1];
                    uint32_t ph = bfpack(s1, s0);
                    ah[q] = ph;
                    float f0 = __uint_as_float(ph << 16);
                    float f1 = __uint_as_float(ph & 0xFFFF0000u);
                    al[q] = bfpack(s1 - f1, s0 - f0);
                }
                const int ksg = half * 2 + ksl;
                uint32_t bh[8][2], bl[8][2];
                #pragma unroll
                for (int nf = 0; nf < 8; nf++) {
                    int ab = (nf * 8 + g) * 36 + 8 * ksg + tg;
                    bh[nf][0] = vhu[ab];
                    bh[nf][1] = vhu[ab + 4];
                    bl[nf][0] = vlu[ab];
                    bl[nf][1] = vlu[ab + 4];
                }
                #pragma unroll
                for (int nf = 0; nf < 8; nf++)
                    mma_bf16(o[nf], ah, bh[nf]);
                #pragma unroll
                for (int nf = 0; nf < 8; nf++)
                    mma_bf16(o[nf], ah, bl[nf]);
                #pragma unroll
                for (int nf = 0; nf < 8; nf++)
                    mma_bf16(o[nf], al, bh[nf]);
            }
            __syncthreads();
        }

        // ---- merge partial O across the warp pair (stages are drained) ----
        float* mb = (float*)smc;
        if (half == 1) {
            #pragma unroll
            for (int nf = 0; nf < 8; nf++)
                #pragma unroll
                for (int r = 0; r < 4; r++)
                    mb[pairid * 1056 + lane * 33 + nf * 4 + r] = o[nf][r];
        }
        __syncthreads();
        if (half == 0) {
            float inv0 = 1.0f / l0, inv1 = 1.0f / l1;
            #pragma unroll
            for (int nf = 0; nf < 8; nf++) {
                float q0v = o[nf][0] + mb[pairid * 1056 + lane * 33 + nf * 4 + 0];
                float q1v = o[nf][1] + mb[pairid * 1056 + lane * 33 + nf * 4 + 1];
                float q2v = o[nf][2] + mb[pairid * 1056 + lane * 33 + nf * 4 + 2];
                float q3v = o[nf][3] + mb[pairid * 1056 + lane * 33 + nf * 4 + 3];
                int col = nf * 8 + 2 * tg;
                long r0 = base + (long)(q0 + rw) * Hn + col;
                *(float2*)&out[r0]          = make_float2(q0v * inv0, q1v * inv0);
                *(float2*)&out[r0 + 8 * Hn] = make_float2(q2v * inv1, q3v * inv1);
            }
        }
        __syncthreads();
    }
}

// ---------------------------------------------------------------------------
extern "C" void kernel_launch(void* const* d_in, const int* in_sizes, int n_in,
                              void* d_out, int out_size)
{
    const float* x  = (const float*)d_in[0];
    const float* Wk = (const float*)d_in[1];
    const float* bk = (const float*)d_in[2];
    const float* Wq = (const float*)d_in[3];
    const float* bq = (const float*)d_in[4];
    const float* Wv = (const float*)d_in[5];
    const float* bv = (const float*)d_in[6];
    float* out = (float*)d_out;

    prep_w<<<(3 * Hn * Cn) / 256, 256>>>(Wk, Wq, Wv);

    cudaFuncSetAttribute(qkv_mma, cudaFuncAttributeMaxDynamicSharedMemorySize, QKV_SMEM);
    qkv_mma<<<(Bn * Tn) / 128, 256, QKV_SMEM>>>(x, bk, bq, bv);

    vt_split<<<dim3(Tn / 64, Bn), 128>>>();

    cudaFuncSetAttribute(attn_mma, cudaFuncAttributeMaxDynamicSharedMemorySize, ATTN_SMEM);
    attn_mma<<<dim3(16, Bn), 256, ATTN_SMEM>>>(out);
}

// round 12
// speedup vs baseline: 1.2334x; 1.1019x over previous
#include <cuda_runtime.h>
#include <cstdint>
#include <math.h>

#define Bn 8
#define Tn 2048
#define Cn 1024
#define Hn 64

// ---------------- device scratch (sanctioned no-alloc path) ----------------
__device__ float g_q[Bn * Tn * Hn];
__device__ float g_k[Bn * Tn * Hn];
__device__ float g_v[Bn * Tn * Hn];                 // V fp32 [b][t][h]
__device__ unsigned short g_vht[Bn * Hn * Tn];      // V bf16 hi, transposed [b][h][t]
__device__ unsigned short g_vlt[Bn * Hn * Tn];      // V bf16 lo, transposed
__device__ unsigned short g_wt_hi[3 * Hn * Cn];     // W bf16 hi, [o*64+n][k]
__device__ unsigned short g_wt_lo[3 * Hn * Cn];     // W bf16 lo

__device__ __forceinline__ float tf32_round(float x) {
    uint32_t u;
    asm("cvt.rna.tf32.f32 %0, %1;" : "=r"(u) : "f"(x));
    return __uint_as_float(u);
}
__device__ __forceinline__ uint32_t bfpack(float hi, float lo) {
    uint32_t d;
    asm("cvt.rn.bf16x2.f32 %0, %1, %2;" : "=r"(d) : "f"(hi), "f"(lo));
    return d;
}
__device__ __forceinline__ uint32_t smem_u32(const void* p) {
    uint32_t a;
    asm("{ .reg .u64 t; cvta.to.shared.u64 t, %1; cvt.u32.u64 %0, t; }" : "=r"(a) : "l"(p));
    return a;
}
__device__ __forceinline__ void cp16(uint32_t s, const void* g) {
    asm volatile("cp.async.cg.shared.global [%0], [%1], 16;" :: "r"(s), "l"(g));
}
#define CP_COMMIT() asm volatile("cp.async.commit_group;" ::: "memory")
#define CP_WAIT1()  asm volatile("cp.async.wait_group 1;" ::: "memory")
#define CP_WAIT0()  asm volatile("cp.async.wait_group 0;" ::: "memory")

__device__ __forceinline__ void mma_tf32(float* c, const uint32_t* a, const uint32_t* b) {
    asm volatile(
        "mma.sync.aligned.m16n8k8.row.col.f32.tf32.tf32.f32 "
        "{%0,%1,%2,%3}, {%4,%5,%6,%7}, {%8,%9}, {%0,%1,%2,%3};"
        : "+f"(c[0]), "+f"(c[1]), "+f"(c[2]), "+f"(c[3])
        : "r"(a[0]), "r"(a[1]), "r"(a[2]), "r"(a[3]), "r"(b[0]), "r"(b[1]));
}
__device__ __forceinline__ void mma_bf16(float* c, const uint32_t* a, const uint32_t* b) {
    asm volatile(
        "mma.sync.aligned.m16n8k16.row.col.f32.bf16.bf16.f32 "
        "{%0,%1,%2,%3}, {%4,%5,%6,%7}, {%8,%9}, {%0,%1,%2,%3};"
        : "+f"(c[0]), "+f"(c[1]), "+f"(c[2]), "+f"(c[3])
        : "r"(a[0]), "r"(a[1]), "r"(a[2]), "r"(a[3]), "r"(b[0]), "r"(b[1]));
}

// ---------------------------------------------------------------------------
// prep: transpose weights to [o][n][k], bf16 Dekker split.  (R8 verbatim)
// ---------------------------------------------------------------------------
__global__ void prep_w(const float* __restrict__ Wk, const float* __restrict__ Wq,
                       const float* __restrict__ Wv) {
    int idx = blockIdx.x * 256 + threadIdx.x;
    int o = idx / (Hn * Cn);
    int rem = idx - o * (Hn * Cn);
    int n = rem / Cn;
    int k = rem - n * Cn;
    const float* W = (o == 0) ? Wq : (o == 1) ? Wk : Wv;
    float v = W[k * Hn + n];
    uint32_t p = bfpack(v, v);
    float fb = __uint_as_float(p & 0xFFFF0000u);
    uint32_t pl = bfpack(v - fb, v - fb);
    g_wt_hi[idx] = (unsigned short)(p >> 16);
    g_wt_lo[idx] = (unsigned short)(pl >> 16);
}

// ---------------------------------------------------------------------------
// V transpose + bf16 split (R8 verbatim)
// ---------------------------------------------------------------------------
__global__ __launch_bounds__(128) void vt_split() {
    __shared__ float ts[64][65];
    const int b = blockIdx.y, t0 = blockIdx.x * 64;
    const int t = threadIdx.x;
    const float* vin = &g_v[((size_t)b * Tn + t0) * Hn];
    #pragma unroll
    for (int i = 0; i < 8; i++) {
        int c = t + i * 128;
        int r = c >> 4, c4 = (c & 15) * 4;
        float4 v = *(const float4*)&vin[r * Hn + c4];
        ts[r][c4] = v.x; ts[r][c4 + 1] = v.y; ts[r][c4 + 2] = v.z; ts[r][c4 + 3] = v.w;
    }
    __syncthreads();
    #pragma unroll
    for (int i = 0; i < 16; i++) {
        int c = t + i * 128;
        int h = c >> 5, c2 = (c & 31) * 2;
        float v0 = ts[c2][h], v1 = ts[c2 + 1][h];
        uint32_t ph = bfpack(v1, v0);
        float f0 = __uint_as_float(ph << 16);
        float f1 = __uint_as_float(ph & 0xFFFF0000u);
        uint32_t pl = bfpack(v1 - f1, v0 - f0);
        size_t o = (size_t)(b * Hn + h) * Tn + t0 + c2;
        *(uint32_t*)&g_vht[o] = ph;
        *(uint32_t*)&g_vlt[o] = pl;
    }
}

// ---------------------------------------------------------------------------
// QKV (R8 verbatim: 128-row CTA, 256 thr, bf16 k16 3-term, double-buffered)
// ---------------------------------------------------------------------------
#define QAST 40
#define QKV_STAGE_B 51200
#define QKV_SMEM (2 * QKV_STAGE_B)

__global__ __launch_bounds__(256) void qkv_mma(
    const float* __restrict__ x,
    const float* __restrict__ bk, const float* __restrict__ bq, const float* __restrict__ bv)
{
    extern __shared__ char smc[];
    const uint32_t sb = smem_u32(smc);
    const int t = threadIdx.x;
    const int wid = t >> 5, lane = t & 31;
    const int wm = wid >> 2, wn = wid & 3;
    const int g = lane >> 2, tg = lane & 3;
    const int m0 = blockIdx.x * 128;

    float c[4][6][4];
    #pragma unroll
    for (int mf = 0; mf < 4; mf++)
        #pragma unroll
        for (int nf = 0; nf < 6; nf++)
            #pragma unroll
            for (int r = 0; r < 4; r++) c[mf][nf][r] = 0.0f;

    auto issue = [&](int ch, int st) {
        const int k0 = ch * 32;
        uint32_t sA = sb + (uint32_t)st * QKV_STAGE_B;
        uint32_t sBh = sA + 20480;
        uint32_t sBl = sBh + 15360;
        #pragma unroll
        for (int i = 0; i < 4; i++) {
            int cc = t + i * 256;
            int r = cc >> 3, o = cc & 7;
            cp16(sA + r * 160 + o * 16, &x[(size_t)(m0 + r) * Cn + k0 + o * 4]);
        }
        #pragma unroll
        for (int i = 0; i < 3; i++) {
            int cc = t + i * 256;
            int r = cc >> 2, o = cc & 3;
            cp16(sBh + r * 80 + o * 16,
                 (const char*)g_wt_hi + ((size_t)r * Cn + k0 + o * 8) * 2);
            cp16(sBl + r * 80 + o * 16,
                 (const char*)g_wt_lo + ((size_t)r * Cn + k0 + o * 8) * 2);
        }
    };

    issue(0, 0);
    CP_COMMIT();

    for (int ch = 0; ch < 32; ch++) {
        if (ch < 31) { issue(ch + 1, (ch + 1) & 1); CP_COMMIT(); CP_WAIT1(); }
        else         { CP_WAIT0(); }
        __syncthreads();

        char* stg = smc + (ch & 1) * QKV_STAGE_B;
        const float* As = (const float*)stg;
        const uint32_t* Bhu = (const uint32_t*)(stg + 20480);
        const uint32_t* Blu = (const uint32_t*)(stg + 35840);

        #pragma unroll
        for (int ks = 0; ks < 2; ks++) {
            const int kk = ks * 16;
            uint32_t a_h[4][4], a_l[4][4], b_h[6][2], b_l[6][2];
            #pragma unroll
            for (int mf = 0; mf < 4; mf++) {
                int row = wm * 64 + mf * 16 + g;
                float2 p0 = *(const float2*)&As[row * QAST + kk + 2 * tg];
                float2 p1 = *(const float2*)&As[(row + 8) * QAST + kk + 2 * tg];
                float2 p2 = *(const float2*)&As[row * QAST + kk + 8 + 2 * tg];
                float2 p3 = *(const float2*)&As[(row + 8) * QAST + kk + 8 + 2 * tg];
                float2 ps[4] = {p0, p1, p2, p3};
                #pragma unroll
                for (int q = 0; q < 4; q++) {
                    uint32_t ph = bfpack(ps[q].y, ps[q].x);
                    a_h[mf][q] = ph;
                    float f0 = __uint_as_float(ph << 16);
                    float f1 = __uint_as_float(ph & 0xFFFF0000u);
                    a_l[mf][q] = bfpack(ps[q].y - f1, ps[q].x - f0);
                }
            }
            #pragma unroll
            for (int nf = 0; nf < 6; nf++) {
                int n = wn * 48 + nf * 8 + g;
                int ab = n * 20 + ks * 8 + tg;
                b_h[nf][0] = Bhu[ab];
                b_h[nf][1] = Bhu[ab + 4];
                b_l[nf][0] = Blu[ab];
                b_l[nf][1] = Blu[ab + 4];
            }
            #pragma unroll
            for (int nf = 0; nf < 6; nf++)
                #pragma unroll
                for (int mf = 0; mf < 4; mf++)
                    mma_bf16(c[mf][nf], a_h[mf], b_h[nf]);
            #pragma unroll
            for (int nf = 0; nf < 6; nf++)
                #pragma unroll
                for (int mf = 0; mf < 4; mf++)
                    mma_bf16(c[mf][nf], a_h[mf], b_l[nf]);
            #pragma unroll
            for (int nf = 0; nf < 6; nf++)
                #pragma unroll
                for (int mf = 0; mf < 4; mf++)
                    mma_bf16(c[mf][nf], a_l[mf], b_h[nf]);
        }
        __syncthreads();
    }

    #pragma unroll
    for (int nf = 0; nf < 6; nf++) {
        int col = wn * 48 + nf * 8 + tg * 2;
        int o = col >> 6;
        int h = col & 63;
        float* gout = (o == 0) ? g_q : (o == 1) ? g_k : g_v;
        const float* bias = (o == 0) ? bq : (o == 1) ? bk : bv;
        float2 bb = *(const float2*)&bias[h];
        #pragma unroll
        for (int mf = 0; mf < 4; mf++) {
            int r0 = m0 + wm * 64 + mf * 16 + g;
            *(float2*)&gout[(size_t)r0 * Hn + h] =
                make_float2(c[mf][nf][0] + bb.x, c[mf][nf][1] + bb.y);
            *(float2*)&gout[(size_t)(r0 + 8) * Hn + h] =
                make_float2(c[mf][nf][2] + bb.x, c[mf][nf][3] + bb.y);
        }
    }
}

// ---------------------------------------------------------------------------
// Flash attention (R8 structure, 128 threads, balanced pairs) with 128-wide
// k-chunks: 2 k-tiles per iteration -> half the barriers/softmax passes.
// Stage: K 128x68 f32 (34816) + VhT 64x68 u32 (17408) + VlT (17408) = 69632 B.
// x2 stages = 139264 B, 1 CTA/SM. Pair totals: 17 chunks for every CTA.
// ---------------------------------------------------------------------------
#define KST 68
#define VST 68
#define ATT_STAGE_B 69632
#define ATTN_SMEM (2 * ATT_STAGE_B)

__global__ __launch_bounds__(128) void attn_mma(float* __restrict__ out)
{
    extern __shared__ char smc[];
    const uint32_t sb = smem_u32(smc);

    const int t = threadIdx.x;
    const int w = t >> 5, lane = t & 31;
    const int g = lane >> 2, tg = lane & 3;
    const int b = blockIdx.y;
    const long base = (long)b * Tn * Hn;
    const float scale = 0.03125f;     // 1024^-0.5

    // one chunk = 128 k-positions
    auto issue = [&](int kc, int st) {
        uint32_t sK = sb + (uint32_t)st * ATT_STAGE_B;
        uint32_t sVh = sK + 34816;
        uint32_t sVl = sVh + 17408;
        #pragma unroll
        for (int i = 0; i < 16; i++) {
            int r = (t >> 4) + i * 8;            // 0..127
            int c4 = (t & 15) * 4;
            cp16(sK + (r * KST + c4) * 4, &g_k[base + (long)(kc + r) * Hn + c4]);
        }
        #pragma unroll
        for (int i = 0; i < 8; i++) {
            int cc = t + i * 128;                // 0..1023
            int h = cc >> 4, o = cc & 15;        // 64 h-rows x 16 chunks
            size_t go = ((size_t)(b * Hn + h) * Tn + kc + o * 8) * 2;
            cp16(sVh + (h * VST + o * 4) * 4, (const char*)g_vht + go);
            cp16(sVl + (h * VST + o * 4) * 4, (const char*)g_vlt + go);
        }
    };

    for (int tloop = 0; tloop < 2; tloop++) {
        const int qi = (tloop == 0) ? blockIdx.x : (31 - blockIdx.x);
        const int q0 = qi * 64;
        const int rw = w * 16 + g;
        const int nch = (qi + 2) >> 1;           // ceil((qi+1)/2)

        issue(0, 0);
        CP_COMMIT();

        uint32_t qa[8][4];
        {
            const float* qp = &g_q[base + (long)(q0 + rw) * Hn];
            #pragma unroll
            for (int ksi = 0; ksi < 8; ksi++) {
                qa[ksi][0] = __float_as_uint(tf32_round(qp[ksi * 8 + tg] * scale));
                qa[ksi][1] = __float_as_uint(tf32_round(qp[8 * Hn + ksi * 8 + tg] * scale));
                qa[ksi][2] = __float_as_uint(tf32_round(qp[ksi * 8 + tg + 4] * scale));
                qa[ksi][3] = __float_as_uint(tf32_round(qp[8 * Hn + ksi * 8 + tg + 4] * scale));
            }
        }

        float m0 = -1e30f, m1 = -1e30f, l0 = 0.0f, l1 = 0.0f;
        float o[8][4];
        #pragma unroll
        for (int nf = 0; nf < 8; nf++)
            #pragma unroll
            for (int r = 0; r < 4; r++) o[nf][r] = 0.0f;

        for (int jj = 0; jj < nch; jj++) {
            if (jj + 1 < nch) { issue((jj + 1) * 128, (jj + 1) & 1); CP_COMMIT(); CP_WAIT1(); }
            else              { CP_WAIT0(); }
            __syncthreads();

            char* stg = smc + (jj & 1) * ATT_STAGE_B;
            const float* ksm = (const float*)stg;
            const uint32_t* vhu = (const uint32_t*)(stg + 34816);
            const uint32_t* vlu = (const uint32_t*)(stg + 52224);

            // ---- S = Qs . K^T over 128 columns ----
            float s[16][4];
            #pragma unroll
            for (int nf = 0; nf < 16; nf++)
                #pragma unroll
                for (int r = 0; r < 4; r++) s[nf][r] = 0.0f;

            #pragma unroll
            for (int ksi = 0; ksi < 8; ksi++) {
                #pragma unroll
                for (int nf = 0; nf < 16; nf++) {
                    uint32_t bf[2];
                    int a = (nf * 8 + g) * KST + ksi * 8 + tg;
                    bf[0] = __float_as_uint(ksm[a]);
                    bf[1] = __float_as_uint(ksm[a + 4]);
                    mma_tf32(s[nf], qa[ksi], bf);
                }
            }

            // ---- causal mask (last chunk only; global comparison) ----
            if (jj == nch - 1) {
                const int kc = jj * 128;
                const int rg0 = q0 + rw, rg1 = rg0 + 8;
                #pragma unroll
                for (int nf = 0; nf < 16; nf++) {
                    int col = kc + nf * 8 + 2 * tg;
                    if (col     > rg0) s[nf][0] = -1e30f;
                    if (col + 1 > rg0) s[nf][1] = -1e30f;
                    if (col     > rg1) s[nf][2] = -1e30f;
                    if (col + 1 > rg1) s[nf][3] = -1e30f;
                }
            }

            // ---- online softmax (single pass over 128 cols) ----
            float mx0 = -1e30f, mx1 = -1e30f;
            #pragma unroll
            for (int nf = 0; nf < 16; nf++) {
                mx0 = fmaxf(mx0, fmaxf(s[nf][0], s[nf][1]));
                mx1 = fmaxf(mx1, fmaxf(s[nf][2], s[nf][3]));
            }
            #pragma unroll
            for (int off = 1; off <= 2; off <<= 1) {
                mx0 = fmaxf(mx0, __shfl_xor_sync(0xffffffffu, mx0, off));
                mx1 = fmaxf(mx1, __shfl_xor_sync(0xffffffffu, mx1, off));
            }
            float mn0 = fmaxf(m0, mx0), mn1 = fmaxf(m1, mx1);
            float rs0 = 0.0f, rs1 = 0.0f;
            #pragma unroll
            for (int nf = 0; nf < 16; nf++) {
                s[nf][0] = __expf(s[nf][0] - mn0);
                s[nf][1] = __expf(s[nf][1] - mn0);
                s[nf][2] = __expf(s[nf][2] - mn1);
                s[nf][3] = __expf(s[nf][3] - mn1);
                rs0 += s[nf][0] + s[nf][1];
                rs1 += s[nf][2] + s[nf][3];
            }
            #pragma unroll
            for (int off = 1; off <= 2; off <<= 1) {
                rs0 += __shfl_xor_sync(0xffffffffu, rs0, off);
                rs1 += __shfl_xor_sync(0xffffffffu, rs1, off);
            }
            float a0 = __expf(m0 - mn0), a1 = __expf(m1 - mn1);
            l0 = l0 * a0 + rs0; m0 = mn0;
            l1 = l1 * a1 + rs1; m1 = mn1;
            #pragma unroll
            for (int nf = 0; nf < 8; nf++) {
                o[nf][0] *= a0; o[nf][1] *= a0;
                o[nf][2] *= a1; o[nf][3] *= a1;
            }

            // ---- O += P . V over 128 k (bf16 k16, 3 terms, local packing) ----
            #pragma unroll
            for (int ksi = 0; ksi < 8; ksi++) {
                uint32_t ah[4], al[4];
                #pragma unroll
                for (int q = 0; q < 4; q++) {
                    int sn = 2 * ksi + (q >> 1);
                    int e = (q & 1) * 2;
                    float s0 = s[sn][e], s1 = s[sn][e + 1];
                    uint32_t ph = bfpack(s1, s0);
                    ah[q] = ph;
                    float f0 = __uint_as_float(ph << 16);
                    float f1 = __uint_as_float(ph & 0xFFFF0000u);
                    al[q] = bfpack(s1 - f1, s0 - f0);
                }
                uint32_t bh[8][2], bl[8][2];
                #pragma unroll
                for (int nf = 0; nf < 8; nf++) {
                    int ab = (nf * 8 + g) * VST + 8 * ksi + tg;
                    bh[nf][0] = vhu[ab];
                    bh[nf][1] = vhu[ab + 4];
                    bl[nf][0] = vlu[ab];
                    bl[nf][1] = vlu[ab + 4];
                }
                #pragma unroll
                for (int nf = 0; nf < 8; nf++)
                    mma_bf16(o[nf], ah, bh[nf]);
                #pragma unroll
                for (int nf = 0; nf < 8; nf++)
                    mma_bf16(o[nf], ah, bl[nf]);
                #pragma unroll
                for (int nf = 0; nf < 8; nf++)
                    mma_bf16(o[nf], al, bh[nf]);
            }
            __syncthreads();
        }

        float inv0 = 1.0f / l0, inv1 = 1.0f / l1;
        #pragma unroll
        for (int nf = 0; nf < 8; nf++) {
            int col = nf * 8 + 2 * tg;
            long r0 = base + (long)(q0 + rw) * Hn + col;
            *(float2*)&out[r0]          = make_float2(o[nf][0] * inv0, o[nf][1] * inv0);
            *(float2*)&out[r0 + 8 * Hn] = make_float2(o[nf][2] * inv1, o[nf][3] * inv1);
        }
    }
}

// ---------------------------------------------------------------------------
extern "C" void kernel_launch(void* const* d_in, const int* in_sizes, int n_in,
                              void* d_out, int out_size)
{
    const float* x  = (const float*)d_in[0];
    const float* Wk = (const float*)d_in[1];
    const float* bk = (const float*)d_in[2];
    const float* Wq = (const float*)d_in[3];
    const float* bq = (const float*)d_in[4];
    const float* Wv = (const float*)d_in[5];
    const float* bv = (const float*)d_in[6];
    float* out = (float*)d_out;

    prep_w<<<(3 * Hn * Cn) / 256, 256>>>(Wk, Wq, Wv);

    cudaFuncSetAttribute(qkv_mma, cudaFuncAttributeMaxDynamicSharedMemorySize, QKV_SMEM);
    qkv_mma<<<(Bn * Tn) / 128, 256, QKV_SMEM>>>(x, bk, bq, bv);

    vt_split<<<dim3(Tn / 64, Bn), 128>>>();

    cudaFuncSetAttribute(attn_mma, cudaFuncAttributeMaxDynamicSharedMemorySize, ATTN_SMEM);
    attn_mma<<<dim3(16, Bn), 128, ATTN_SMEM>>>(out);
}